// round 2
// baseline (speedup 1.0000x reference)
#include <cuda_runtime.h>

#define BB 2
#define CC 256
#define HN 65536           // H*W
#define NL 8
#define NPAD (HN + 512)    // 64-aligned per-label segments
#define NBLK 256           // HN / 256

// ---------------- static device scratch (zero-initialized) ----------------
__device__ int   g_is32;                         // 1 if masks are int32, 0 if int64
__device__ int   g_perm[2][NPAD];
__device__ int   g_hist[2][NBLK * NL];
__device__ int   g_base[2][NBLK * NL];
__device__ int   g_aoff[2][NL + 1];
__device__ int   g_cnt[2][NL];
__device__ int   g_guide[NL];
__device__ float g_Xc[BB * CC * NPAD];           // gathered content (padding stays 0)
__device__ float g_Xs[BB * CC * NPAD];           // gathered style
__device__ float g_mean[2][NL * BB * CC];
__device__ float g_cov[2][NL * BB * CC * CC];
__device__ float g_L[2][NL * BB * CC * CC];      // chol factors (c and s)
__device__ float g_T[NL * BB * CC * CC];         // T = Ls * inv(Lc), lower-tri
__device__ float g_v[NL * BB * CC];              // v = mu_s - T*mu_c

__constant__ int c_pt[10] = {0,1,1,2,2,2,3,3,3,3};
__constant__ int c_pd[10] = {0,0,1,0,1,2,0,1,2,3};

// ---------------- mask dtype sniffer ----------------
// Reads the first HN 32-bit words of c_mask (in-bounds whether the buffer is
// HN int32s or HN int64s). If masks are int64 (labels 0..7), every odd word
// (high half) is zero. If int32, odd words are labels and some are nonzero
// with probability ~1.
__global__ void k_sniff(const unsigned* __restrict__ m) {
    __shared__ unsigned red[256];
    unsigned v = 0;
    for (int i = threadIdx.x * 2 + 1; i < HN; i += 512) v |= m[i];
    red[threadIdx.x] = v;
    __syncthreads();
    for (int k = 128; k > 0; k >>= 1) {
        if (threadIdx.x < k) red[threadIdx.x] |= red[threadIdx.x + k];
        __syncthreads();
    }
    if (threadIdx.x == 0) g_is32 = (red[0] != 0u) ? 1 : 0;
}

__device__ __forceinline__ int get_label(const void* mask, int p) {
    if (g_is32) return ((const int*)mask)[p];
    return (int)((const long long*)mask)[p];
}

// ---------------- counting sort (deterministic, stable) ----------------
__global__ void k_hist(const void* mask, int sel) {
    __shared__ int h[NL];
    int t = threadIdx.x;
    if (t < NL) h[t] = 0;
    __syncthreads();
    int lab = get_label(mask, blockIdx.x * 256 + t);
    atomicAdd(&h[lab], 1);
    __syncthreads();
    if (t < NL) g_hist[sel][blockIdx.x * NL + t] = h[t];
}

__global__ void k_scan(int sel) {
    __shared__ int tot[NL];
    int t = threadIdx.x;
    if (t < NL) {
        int s = 0;
        for (int b = 0; b < NBLK; b++) { g_base[sel][b * NL + t] = s; s += g_hist[sel][b * NL + t]; }
        tot[t] = s;
        g_cnt[sel][t] = s;
    }
    __syncthreads();
    if (t == 0) {
        int off = 0;
        for (int q = 0; q < NL; q++) { g_aoff[sel][q] = off; off += (tot[q] + 63) & ~63; }
        g_aoff[sel][NL] = off;
    }
    __syncthreads();
    if (t < NL) {
        int o = g_aoff[sel][t];
        for (int b = 0; b < NBLK; b++) g_base[sel][b * NL + t] += o;
    }
}

__global__ void k_guide() {
    int l = threadIdx.x;
    if (l >= NL) return;
    float a = (float)g_cnt[0][l], b = (float)g_cnt[1][l];
    g_guide[l] = (a > 10.f && b > 10.f && a < 10.f * b && b < 10.f * a) ? 1 : 0;
}

__global__ void k_perminit() {
    int i = blockIdx.x * 256 + threadIdx.x;
    if (i < NPAD) { g_perm[0][i] = -1; g_perm[1][i] = -1; }
}

__global__ void k_scatter(const void* mask, int sel) {
    __shared__ int labs[256];
    int t = threadIdx.x;
    int p = blockIdx.x * 256 + t;
    int lab = get_label(mask, p);
    labs[t] = lab;
    __syncthreads();
    int rank = 0;
    for (int i = 0; i < t; i++) rank += (labs[i] == lab);
    g_perm[sel][g_base[sel][blockIdx.x * NL + lab] + rank] = p;
}

// ---------------- gather into label-sorted dense layout ----------------
__global__ __launch_bounds__(256) void k_gather(const float* __restrict__ src, int sel) {
    int j  = blockIdx.x * 256 + threadIdx.x;       // slot
    int bc = blockIdx.y;
    int p = g_perm[sel][j];
    if (p < 0) return;                              // padding slot (stays 0)
    float* dst = sel ? g_Xs : g_Xc;
    dst[(size_t)bc * NPAD + j] = src[(size_t)bc * HN + p];
}

// ---------------- per-label per-batch channel means ----------------
__global__ __launch_bounds__(256) void k_mean(int sel) {
    int l = blockIdx.z, b = blockIdx.y, c = blockIdx.x;
    if (!g_guide[l]) return;
    const float* X = sel ? g_Xs : g_Xc;
    int start = g_aoff[sel][l], n = g_cnt[sel][l];
    const float* row = X + (size_t)(b * CC + c) * NPAD + start;
    float s = 0.f;
    for (int j = threadIdx.x; j < n; j += 256) s += row[j];
    __shared__ float red[256];
    red[threadIdx.x] = s;
    __syncthreads();
    for (int k = 128; k > 0; k >>= 1) {
        if (threadIdx.x < k) red[threadIdx.x] += red[threadIdx.x + k];
        __syncthreads();
    }
    if (threadIdx.x == 0)
        g_mean[sel][(l * BB + b) * CC + c] = red[0] / (float)n;
}

// ---------------- covariance: 64x64 tiles, symmetric pairs ----------------
__global__ __launch_bounds__(256) void k_cov(int sel) {
    int pair = blockIdx.x;
    int lb = blockIdx.y, l = lb / BB, b = lb % BB;
    if (!g_guide[l]) return;
    int ct = c_pt[pair], dt = c_pd[pair];
    const float* X = sel ? g_Xs : g_Xc;
    int start = g_aoff[sel][l], n = g_cnt[sel][l];

    __shared__ float As[32][65];
    __shared__ float Bs[32][65];
    int t = threadIdx.x, tx = t & 15, ty = t >> 4;
    int ty4 = ty * 4, tx4 = tx * 4;
    float acc[4][4] = {};

    const float* Xa = X + (size_t)(b * CC + ct * 64) * NPAD + start;
    const float* Xb = X + (size_t)(b * CC + dt * 64) * NPAD + start;

    for (int k0 = 0; k0 < n; k0 += 32) {            // tail reads hit zero padding
        #pragma unroll
        for (int it = 0; it < 8; it++) {
            int idx = t + it * 256;
            int c = idx >> 5, k = idx & 31;
            As[k][c] = Xa[(size_t)c * NPAD + k0 + k];
            Bs[k][c] = Xb[(size_t)c * NPAD + k0 + k];
        }
        __syncthreads();
        #pragma unroll
        for (int k = 0; k < 32; k++) {
            float av[4], bv[4];
            #pragma unroll
            for (int i = 0; i < 4; i++) av[i] = As[k][ty4 + i];
            #pragma unroll
            for (int j = 0; j < 4; j++) bv[j] = Bs[k][tx4 + j];
            #pragma unroll
            for (int i = 0; i < 4; i++)
                #pragma unroll
                for (int j = 0; j < 4; j++) acc[i][j] += av[i] * bv[j];
        }
        __syncthreads();
    }

    float a = (float)n;
    float inv = 1.f / (a - 1.f);
    const float* mu = g_mean[sel] + (l * BB + b) * CC;
    float* cov = g_cov[sel] + (size_t)(l * BB + b) * CC * CC;
    #pragma unroll
    for (int i = 0; i < 4; i++) {
        int r = ct * 64 + ty4 + i;
        float mur = mu[r];
        #pragma unroll
        for (int j = 0; j < 4; j++) {
            int cidx = dt * 64 + tx4 + j;
            float val = (acc[i][j] - a * mur * mu[cidx]) * inv;
            cov[r * CC + cidx] = val;
            if (ct != dt) cov[cidx * CC + r] = val;
        }
    }
}

// ---------------- Cholesky (right-looking, in global, per-matrix block) ----------------
__global__ __launch_bounds__(256) void k_chol() {
    int m = blockIdx.x;            // 0..31 : first 16 = content, next 16 = style
    int sel = m >> 4;
    int mm = m & 15;
    int l = mm / BB;
    if (!g_guide[l]) return;
    const float* A = g_cov[sel] + (size_t)mm * CC * CC;
    float* Lm = g_L[sel] + (size_t)mm * CC * CC;
    int t = threadIdx.x;
    for (int idx = t; idx < CC * CC; idx += 256) {
        int r = idx >> 8, c = idx & 255;
        Lm[idx] = (c <= r) ? A[idx] : 0.f;
    }
    __syncthreads();
    __shared__ float colk[CC];
    int tx = t & 31, ty = t >> 5;   // 8 x 32
    for (int k = 0; k < CC; k++) {
        if (t == 0) Lm[k * CC + k] = sqrtf(Lm[k * CC + k]);
        __syncthreads();
        float d = Lm[k * CC + k];
        for (int i = k + 1 + t; i < CC; i += 256) {
            float vv = Lm[i * CC + k] / d;
            Lm[i * CC + k] = vv;
            colk[i] = vv;
        }
        __syncthreads();
        for (int i = k + 1 + ty; i < CC; i += 8) {
            float ci = colk[i];
            for (int j = k + 1 + tx; j <= i; j += 32)
                Lm[i * CC + j] -= ci * colk[j];
        }
        __syncthreads();
    }
}

// ---------------- solve T * Lc = Ls (row-wise back substitution) ----------------
__global__ __launch_bounds__(256) void k_solveT() {
    int m = blockIdx.x;             // l*BB+b
    int l = m / BB;
    if (!g_guide[l]) return;
    const float* Lc = g_L[0] + (size_t)m * CC * CC;
    const float* Ls = g_L[1] + (size_t)m * CC * CC;
    float* T = g_T + (size_t)m * CC * CC;
    int r = threadIdx.x;
    float* x = T + r * CC;
    for (int k = r + 1; k < CC; k++) x[k] = 0.f;
    for (int k = r; k >= 0; k--) {
        float s0 = 0.f, s1 = 0.f, s2 = 0.f, s3 = 0.f;
        int m2 = k + 1;
        for (; m2 + 3 <= r; m2 += 4) {
            s0 += Lc[(m2    ) * CC + k] * x[m2    ];
            s1 += Lc[(m2 + 1) * CC + k] * x[m2 + 1];
            s2 += Lc[(m2 + 2) * CC + k] * x[m2 + 2];
            s3 += Lc[(m2 + 3) * CC + k] * x[m2 + 3];
        }
        for (; m2 <= r; m2++) s0 += Lc[m2 * CC + k] * x[m2];
        float s = Ls[r * CC + k] - (s0 + s1 + s2 + s3);
        x[k] = s / Lc[k * CC + k];
    }
}

// ---------------- v = mu_s - T * mu_c ----------------
__global__ __launch_bounds__(256) void k_v() {
    int m = blockIdx.x, l = m / BB;
    if (!g_guide[l]) return;
    int c = threadIdx.x;
    const float* T = g_T + (size_t)m * CC * CC + c * CC;
    const float* muc = g_mean[0] + m * CC;
    float s = 0.f;
    for (int e = 0; e <= c; e++) s += T[e] * muc[e];
    g_v[m * CC + c] = g_mean[1][m * CC + c] - s;
}

// ---------------- out = c_feat (base copy) ----------------
__global__ __launch_bounds__(256) void k_copy(const float* __restrict__ src, float* __restrict__ dst) {
    size_t i = (size_t)blockIdx.x * 256 + threadIdx.x;
    float4 v = ((const float4*)src)[i];
    ((float4*)dst)[i] = v;
}

// ---------------- apply: out[:,p] = T * x + v, scattered ----------------
__global__ __launch_bounds__(256) void k_apply(float* __restrict__ out) {
    int pt = blockIdx.x;            // pixel tile over padded slots
    int ct = blockIdx.y;            // output channel tile
    int b  = blockIdx.z;
    int col0 = pt * 64;
    int l = 0;
    #pragma unroll
    for (int q = 1; q < NL; q++) if (g_aoff[0][q] <= col0) l = q;
    if (!g_guide[l]) return;
    int start = g_aoff[0][l], n = g_cnt[0][l];
    int local0 = col0 - start;
    if (local0 >= n) return;

    const float* T = g_T + (size_t)(l * BB + b) * CC * CC;
    const float* vv = g_v + (l * BB + b) * CC;

    __shared__ float At[32][65];
    __shared__ float Bx[32][65];
    int t = threadIdx.x, tx = t & 15, ty = t >> 4;
    int ty4 = ty * 4, tx4 = tx * 4;
    float acc[4][4] = {};

    int kend = (ct + 1) * 64;       // T lower-triangular
    for (int k0 = 0; k0 < kend; k0 += 32) {
        #pragma unroll
        for (int it = 0; it < 8; it++) {
            int idx = t + it * 256;
            {   // A: 64 rows (out channels) x 32 k, coalesced along T rows
                int cA = idx >> 5, kA = idx & 31;
                At[kA][cA] = T[(size_t)(ct * 64 + cA) * CC + k0 + kA];
            }
            {   // B: 32 k (in channels) x 64 pixels, coalesced along pixels
                int px = idx & 63, kB = idx >> 6;
                Bx[kB][px] = g_Xc[(size_t)(b * CC + k0 + kB) * NPAD + col0 + px];
            }
        }
        __syncthreads();
        #pragma unroll
        for (int k = 0; k < 32; k++) {
            float av[4], bv[4];
            #pragma unroll
            for (int i = 0; i < 4; i++) av[i] = At[k][ty4 + i];
            #pragma unroll
            for (int j = 0; j < 4; j++) bv[j] = Bx[k][tx4 + j];
            #pragma unroll
            for (int i = 0; i < 4; i++)
                #pragma unroll
                for (int j = 0; j < 4; j++) acc[i][j] += av[i] * bv[j];
        }
        __syncthreads();
    }

    #pragma unroll
    for (int j = 0; j < 4; j++) {
        int lc = local0 + tx4 + j;
        if (lc >= n) continue;
        int p = g_perm[0][col0 + tx4 + j];
        #pragma unroll
        for (int i = 0; i < 4; i++) {
            int c = ct * 64 + ty4 + i;
            out[(size_t)(b * CC + c) * HN + p] = acc[i][j] + vv[c];
        }
    }
}

// ---------------- launcher ----------------
extern "C" void kernel_launch(void* const* d_in, const int* in_sizes, int n_in,
                              void* d_out, int out_size) {
    const float* c_feat = (const float*)d_in[0];
    const float* s_feat = (const float*)d_in[1];
    const void* c_mask = d_in[2];
    const void* s_mask = d_in[3];
    float* out = (float*)d_out;

    k_sniff<<<1, 256>>>((const unsigned*)c_mask);

    k_hist<<<NBLK, 256>>>(c_mask, 0);
    k_hist<<<NBLK, 256>>>(s_mask, 1);
    k_scan<<<1, 32>>>(0);
    k_scan<<<1, 32>>>(1);
    k_guide<<<1, 32>>>();
    k_perminit<<<NPAD / 256, 256>>>();
    k_scatter<<<NBLK, 256>>>(c_mask, 0);
    k_scatter<<<NBLK, 256>>>(s_mask, 1);

    dim3 gg(NPAD / 256, BB * CC);
    k_gather<<<gg, 256>>>(c_feat, 0);
    k_gather<<<gg, 256>>>(s_feat, 1);

    dim3 gm(CC, BB, NL);
    k_mean<<<gm, 256>>>(0);
    k_mean<<<gm, 256>>>(1);

    dim3 gc(10, NL * BB);
    k_cov<<<gc, 256>>>(0);
    k_cov<<<gc, 256>>>(1);

    k_chol<<<32, 256>>>();
    k_solveT<<<NL * BB, 256>>>();
    k_v<<<NL * BB, 256>>>();

    k_copy<<<(BB * CC * HN / 4) / 256, 256>>>(c_feat, out);

    dim3 ga(NPAD / 64, 4, BB);
    k_apply<<<ga, 256>>>(out);
}

// round 5
// speedup vs baseline: 1.2890x; 1.2890x over previous
#include <cuda_runtime.h>

#define BB 2
#define CC 256
#define HN 65536           // H*W
#define NL 8
#define NPAD (HN + 512)    // 64-aligned per-label segments
#define NBLK 256           // HN / 256

// ---------------- static device scratch (zero-initialized) ----------------
__device__ int   g_is32;                         // 1 if masks are int32, 0 if int64
__device__ int   g_perm[2][NPAD];
__device__ int   g_slot[HN];                     // pixel -> slot if guided else -1
__device__ int   g_hist[2][NBLK * NL];
__device__ int   g_base[2][NBLK * NL];
__device__ int   g_aoff[2][NL + 1];
__device__ int   g_cnt[2][NL];
__device__ int   g_guide[NL];
__device__ float g_Xc[BB * CC * NPAD];           // gathered content (padding stays 0)
__device__ float g_Xs[BB * CC * NPAD];           // gathered style
__device__ float g_Y[BB * CC * NPAD];            // dense colored output
__device__ float g_mean[2][NL * BB * CC];
__device__ float g_cov[2][NL * BB * CC * CC];
__device__ float g_L[2][NL * BB * CC * CC];      // chol factors (c and s)
__device__ float g_T[NL * BB * CC * CC];         // T = Ls * inv(Lc), lower-tri
__device__ float g_v[NL * BB * CC];              // v = mu_s - T*mu_c

__constant__ int c_pt[10] = {0,1,1,2,2,2,3,3,3,3};
__constant__ int c_pd[10] = {0,0,1,0,1,2,0,1,2,3};

// ---------------- mask dtype sniffer ----------------
__global__ void k_sniff(const unsigned* __restrict__ m) {
    __shared__ unsigned red[256];
    unsigned v = 0;
    for (int i = threadIdx.x * 2 + 1; i < HN; i += 512) v |= m[i];
    red[threadIdx.x] = v;
    __syncthreads();
    for (int k = 128; k > 0; k >>= 1) {
        if (threadIdx.x < k) red[threadIdx.x] |= red[threadIdx.x + k];
        __syncthreads();
    }
    if (threadIdx.x == 0) g_is32 = (red[0] != 0u) ? 1 : 0;
}

__device__ __forceinline__ int get_label(const void* mask, int p) {
    if (g_is32) return ((const int*)mask)[p];
    return (int)((const long long*)mask)[p];
}

// ---------------- counting sort (deterministic, stable) ----------------
__global__ void k_hist(const void* mask, int sel) {
    __shared__ int h[NL];
    int t = threadIdx.x;
    if (t < NL) h[t] = 0;
    __syncthreads();
    int lab = get_label(mask, blockIdx.x * 256 + t);
    atomicAdd(&h[lab], 1);
    __syncthreads();
    if (t < NL) g_hist[sel][blockIdx.x * NL + t] = h[t];
}

// parallel scan: warp w handles label w; lane sums 8 block-histograms
__global__ void k_scan(int sel) {
    __shared__ int sh[NL][NBLK];
    __shared__ int ltot[NL];
    __shared__ int laoff[NL];
    int t = threadIdx.x, w = t >> 5, lane = t & 31;
    for (int i = t; i < NL * NBLK; i += 256) {
        int b = i >> 3, l = i & 7;
        sh[l][b] = g_hist[sel][i];
    }
    __syncthreads();
    int s = 0;
    #pragma unroll
    for (int j = 0; j < 8; j++) s += sh[w][lane * 8 + j];
    int inc = s;
    #pragma unroll
    for (int d = 1; d < 32; d <<= 1) {
        int v = __shfl_up_sync(0xFFFFFFFFu, inc, d);
        if (lane >= d) inc += v;
    }
    int exc = inc - s;
    if (lane == 31) ltot[w] = inc;
    __syncthreads();
    if (t == 0) {
        int off = 0;
        for (int q = 0; q < NL; q++) {
            g_aoff[sel][q] = off;
            laoff[q] = off;
            g_cnt[sel][q] = ltot[q];
            off += (ltot[q] + 63) & ~63;
        }
        g_aoff[sel][NL] = off;
    }
    __syncthreads();
    int run = laoff[w] + exc;
    #pragma unroll
    for (int j = 0; j < 8; j++) {
        int b = lane * 8 + j;
        g_base[sel][b * NL + w] = run;
        run += sh[w][b];
    }
}

__global__ void k_guide() {
    int l = threadIdx.x;
    if (l >= NL) return;
    float a = (float)g_cnt[0][l], b = (float)g_cnt[1][l];
    g_guide[l] = (a > 10.f && b > 10.f && a < 10.f * b && b < 10.f * a) ? 1 : 0;
}

__global__ void k_perminit() {
    int i = blockIdx.x * 256 + threadIdx.x;
    if (i < NPAD) { g_perm[0][i] = -1; g_perm[1][i] = -1; }
}

__global__ void k_scatter(const void* mask, int sel) {
    __shared__ int labs[256];
    int t = threadIdx.x;
    int p = blockIdx.x * 256 + t;
    int lab = get_label(mask, p);
    labs[t] = lab;
    __syncthreads();
    int rank = 0;
    for (int i = 0; i < t; i++) rank += (labs[i] == lab);
    int slot = g_base[sel][blockIdx.x * NL + lab] + rank;
    g_perm[sel][slot] = p;
    if (sel == 0) g_slot[p] = g_guide[lab] ? slot : -1;
}

// ---------------- gather into label-sorted dense layout ----------------
__global__ __launch_bounds__(256) void k_gather(const float* __restrict__ src, int sel) {
    int j  = blockIdx.x * 256 + threadIdx.x;       // slot
    int bc = blockIdx.y;
    int p = g_perm[sel][j];
    if (p < 0) return;                              // padding slot (stays 0)
    float* dst = sel ? g_Xs : g_Xc;
    dst[(size_t)bc * NPAD + j] = src[(size_t)bc * HN + p];
}

// ---------------- per-label per-batch channel means ----------------
__global__ __launch_bounds__(256) void k_mean(int sel) {
    int l = blockIdx.z, b = blockIdx.y, c = blockIdx.x;
    if (!g_guide[l]) return;
    const float* X = sel ? g_Xs : g_Xc;
    int start = g_aoff[sel][l], n = g_cnt[sel][l];
    const float* row = X + (size_t)(b * CC + c) * NPAD + start;
    float s = 0.f;
    for (int j = threadIdx.x; j < n; j += 256) s += row[j];
    __shared__ float red[256];
    red[threadIdx.x] = s;
    __syncthreads();
    for (int k = 128; k > 0; k >>= 1) {
        if (threadIdx.x < k) red[threadIdx.x] += red[threadIdx.x + k];
        __syncthreads();
    }
    if (threadIdx.x == 0)
        g_mean[sel][(l * BB + b) * CC + c] = red[0] / (float)n;
}

// ---------------- covariance: 64x64 tiles, symmetric pairs, float4 smem ----------------
__global__ __launch_bounds__(256) void k_cov(int sel) {
    int pair = blockIdx.x;
    int lb = blockIdx.y, l = lb / BB, b = lb % BB;
    if (!g_guide[l]) return;
    int ct = c_pt[pair], dt = c_pd[pair];
    const float* X = sel ? g_Xs : g_Xc;
    int start = g_aoff[sel][l], n = g_cnt[sel][l];

    __shared__ __align__(16) float As[32][68];
    __shared__ __align__(16) float Bs[32][68];
    int t = threadIdx.x, tx = t & 15, ty = t >> 4;
    int ty4 = ty * 4, tx4 = tx * 4;
    float acc[4][4] = {};

    const float* Xa = X + (size_t)(b * CC + ct * 64) * NPAD + start;
    const float* Xb = X + (size_t)(b * CC + dt * 64) * NPAD + start;

    for (int k0 = 0; k0 < n; k0 += 32) {            // tail reads hit zero padding
        #pragma unroll
        for (int it = 0; it < 8; it++) {
            int idx = t + it * 256;
            int c = idx >> 5, k = idx & 31;
            As[k][c] = Xa[(size_t)c * NPAD + k0 + k];
            Bs[k][c] = Xb[(size_t)c * NPAD + k0 + k];
        }
        __syncthreads();
        #pragma unroll
        for (int k = 0; k < 32; k++) {
            float4 a4 = *(const float4*)&As[k][ty4];
            float4 b4 = *(const float4*)&Bs[k][tx4];
            float av[4] = {a4.x, a4.y, a4.z, a4.w};
            float bv[4] = {b4.x, b4.y, b4.z, b4.w};
            #pragma unroll
            for (int i = 0; i < 4; i++)
                #pragma unroll
                for (int j = 0; j < 4; j++) acc[i][j] += av[i] * bv[j];
        }
        __syncthreads();
    }

    float a = (float)n;
    float inv = 1.f / (a - 1.f);
    const float* mu = g_mean[sel] + (l * BB + b) * CC;
    float* cov = g_cov[sel] + (size_t)(l * BB + b) * CC * CC;
    #pragma unroll
    for (int i = 0; i < 4; i++) {
        int r = ct * 64 + ty4 + i;
        float mur = mu[r];
        #pragma unroll
        for (int j = 0; j < 4; j++) {
            int cidx = dt * 64 + tx4 + j;
            float val = (acc[i][j] - a * mur * mu[cidx]) * inv;
            cov[r * CC + cidx] = val;
            if (ct != dt) cov[cidx * CC + r] = val;
        }
    }
}

// ---------------- blocked Cholesky: 32-col panel in smem, syrk trailing ----------------
__global__ __launch_bounds__(256) void k_chol() {
    int m = blockIdx.x;            // 0..31 : first 16 = content, next 16 = style
    int sel = m >> 4;
    int mm = m & 15;
    int l = mm / BB;
    if (!g_guide[l]) return;
    const float* A = g_cov[sel] + (size_t)mm * CC * CC;
    float* Lm = g_L[sel] + (size_t)mm * CC * CC;
    int t = threadIdx.x;
    for (int i = t; i < CC * CC; i += 256) Lm[i] = A[i];   // upper junk never read
    __syncthreads();

    __shared__ float P[256][33];
    for (int kp = 0; kp < CC; kp += 32) {
        int nr = CC - kp;
        for (int i = t; i < nr * 32; i += 256) {           // load panel
            int r = i >> 5, c = i & 31;
            P[r][c] = Lm[(size_t)(kp + r) * CC + kp + c];
        }
        __syncthreads();
        for (int j = 0; j < 32; j++) {                     // factor 32 columns
            if (t == 0) P[j][j] = sqrtf(P[j][j]);
            __syncthreads();
            float invd = 1.f / P[j][j];
            for (int i = j + 1 + t; i < nr; i += 256) P[i][j] *= invd;
            __syncthreads();
            int tx = t & 31, ty = t >> 5;
            if (tx > j) {
                float pj = P[tx][j];
                for (int i = j + 1 + ty; i < nr; i += 8) P[i][tx] -= P[i][j] * pj;
            }
            __syncthreads();
        }
        for (int i = t; i < nr * 32; i += 256) {           // write panel back
            int r = i >> 5, c = i & 31;
            Lm[(size_t)(kp + r) * CC + kp + c] = P[r][c];
        }
        int base = kp + 32;
        int ntr = CC - base;
        if (ntr > 0) {                                     // trailing syrk
            int nt = (ntr + 63) >> 6;
            int tx = t & 15, ty = t >> 4;
            for (int ti = 0; ti < nt; ti++)
            for (int tj = 0; tj <= ti; tj++) {
                int r0 = base + ti * 64 + ty * 4;
                int c0 = base + tj * 64 + tx * 4;
                float acc[4][4] = {};
                #pragma unroll
                for (int k = 0; k < 32; k++) {
                    float av[4], bv[4];
                    #pragma unroll
                    for (int i = 0; i < 4; i++) av[i] = (r0 + i < CC) ? P[r0 + i - kp][k] : 0.f;
                    #pragma unroll
                    for (int j = 0; j < 4; j++) bv[j] = (c0 + j < CC) ? P[c0 + j - kp][k] : 0.f;
                    #pragma unroll
                    for (int i = 0; i < 4; i++)
                        #pragma unroll
                        for (int j = 0; j < 4; j++) acc[i][j] += av[i] * bv[j];
                }
                #pragma unroll
                for (int i = 0; i < 4; i++) {
                    if (r0 + i >= CC) continue;
                    float* rowp = Lm + (size_t)(r0 + i) * CC;
                    #pragma unroll
                    for (int j = 0; j < 4; j++)
                        if (c0 + j < CC) rowp[c0 + j] -= acc[i][j];
                }
            }
        }
        __syncthreads();
    }
}

// ---------------- solve T * Lc = Ls, Lc column-packed in dynamic smem ----------------
__global__ __launch_bounds__(256) void k_solveT() {
    int m = blockIdx.x;             // l*BB+b
    int l = m / BB;
    if (!g_guide[l]) return;
    const float* Lc = g_L[0] + (size_t)m * CC * CC;
    const float* Ls = g_L[1] + (size_t)m * CC * CC;
    float* T = g_T + (size_t)m * CC * CC;
    extern __shared__ float ct[];   // 32896 floats: col-packed lower triangle
    int t = threadIdx.x;
    // ct[cb(c) + r - c] = Lc[r][c], cb(c) = c*CC - c(c-1)/2
    for (int idx = t; idx < 32896; idx += 256) {
        float fr = (sqrtf(8.f * (float)idx + 1.f) - 1.f) * 0.5f;
        int r = (int)fr;
        if ((r + 1) * (r + 2) / 2 <= idx) r++;
        if (r * (r + 1) / 2 > idx) r--;
        int c = idx - r * (r + 1) / 2;
        int cb = c * CC - (c * (c - 1)) / 2;
        ct[cb + r - c] = Lc[(size_t)r * CC + c];
    }
    __syncthreads();

    int r = t;
    float x[CC];
    #pragma unroll 8
    for (int k = 0; k < CC; k++) x[k] = 0.f;
    const float* lsr = Ls + (size_t)r * CC;
    for (int k = r; k >= 0; k--) {
        int cb = k * CC - (k * (k - 1)) / 2;
        const float* col = ct + cb - k;        // col[i] = Lc[i][k]
        float s0 = 0.f, s1 = 0.f, s2 = 0.f, s3 = 0.f;
        int i = k + 1;
        for (; i + 3 <= r; i += 4) {
            s0 += col[i    ] * x[i    ];
            s1 += col[i + 1] * x[i + 1];
            s2 += col[i + 2] * x[i + 2];
            s3 += col[i + 3] * x[i + 3];
        }
        for (; i <= r; i++) s0 += col[i] * x[i];
        x[k] = (lsr[k] - (s0 + s1 + s2 + s3)) / col[k];
    }
    float* trow = T + (size_t)r * CC;
    for (int k = 0; k < CC; k++) trow[k] = x[k];
}

// ---------------- v = mu_s - T * mu_c ----------------
__global__ __launch_bounds__(256) void k_v() {
    int m = blockIdx.x, l = m / BB;
    if (!g_guide[l]) return;
    int c = threadIdx.x;
    const float* T = g_T + (size_t)m * CC * CC + (size_t)c * CC;
    const float* muc = g_mean[0] + m * CC;
    float s = 0.f;
    for (int e = 0; e <= c; e++) s += T[e] * muc[e];
    g_v[m * CC + c] = g_mean[1][m * CC + c] - s;
}

// ---------------- apply: Y[:,slot] = T * x + v  (dense, coalesced) ----------------
__global__ __launch_bounds__(256) void k_apply() {
    int pt = blockIdx.x;            // pixel tile over padded slots
    int ctile = blockIdx.y;         // output channel tile
    int b  = blockIdx.z;
    int col0 = pt * 64;
    int l = 0;
    #pragma unroll
    for (int q = 1; q < NL; q++) if (g_aoff[0][q] <= col0) l = q;
    if (!g_guide[l]) return;
    int start = g_aoff[0][l], n = g_cnt[0][l];
    if (col0 - start >= n) return;

    const float* T = g_T + (size_t)(l * BB + b) * CC * CC;
    const float* vv = g_v + (l * BB + b) * CC;

    __shared__ __align__(16) float At[32][68];
    __shared__ __align__(16) float Bx[32][68];
    int t = threadIdx.x, tx = t & 15, ty = t >> 4;
    int ty4 = ty * 4, tx4 = tx * 4;
    float acc[4][4] = {};

    int kend = (ctile + 1) * 64;    // T lower-triangular
    for (int k0 = 0; k0 < kend; k0 += 32) {
        #pragma unroll
        for (int it = 0; it < 8; it++) {
            int idx = t + it * 256;
            {
                int cA = idx >> 5, kA = idx & 31;
                At[kA][cA] = T[(size_t)(ctile * 64 + cA) * CC + k0 + kA];
            }
            {
                int px = idx & 63, kB = idx >> 6;
                Bx[kB][px] = g_Xc[(size_t)(b * CC + k0 + kB) * NPAD + col0 + px];
            }
        }
        __syncthreads();
        #pragma unroll
        for (int k = 0; k < 32; k++) {
            float4 a4 = *(const float4*)&At[k][ty4];
            float4 b4 = *(const float4*)&Bx[k][tx4];
            float av[4] = {a4.x, a4.y, a4.z, a4.w};
            float bv[4] = {b4.x, b4.y, b4.z, b4.w};
            #pragma unroll
            for (int i = 0; i < 4; i++)
                #pragma unroll
                for (int j = 0; j < 4; j++) acc[i][j] += av[i] * bv[j];
        }
        __syncthreads();
    }

    #pragma unroll
    for (int i = 0; i < 4; i++) {
        int c = ctile * 64 + ty4 + i;
        float vc = vv[c];
        float4 o = make_float4(acc[i][0] + vc, acc[i][1] + vc, acc[i][2] + vc, acc[i][3] + vc);
        *(float4*)&g_Y[(size_t)(b * CC + c) * NPAD + col0 + tx4] = o;
    }
}

// ---------------- combine: out = slot<0 ? c_feat : Y[slot]  (coalesced) ----------------
__global__ __launch_bounds__(256) void k_combine(const float* __restrict__ cf, float* __restrict__ out) {
    int bc = blockIdx.y;
    size_t base = (size_t)bc * HN;
    int p0 = (blockIdx.x * 256 + threadIdx.x) * 4;
    const float* Yrow = g_Y + (size_t)bc * NPAD;
    float4 f = *(const float4*)&cf[base + p0];
    int4 s = *(const int4*)&g_slot[p0];
    float4 o;
    o.x = (s.x >= 0) ? Yrow[s.x] : f.x;
    o.y = (s.y >= 0) ? Yrow[s.y] : f.y;
    o.z = (s.z >= 0) ? Yrow[s.z] : f.z;
    o.w = (s.w >= 0) ? Yrow[s.w] : f.w;
    *(float4*)&out[base + p0] = o;
}

// ---------------- launcher ----------------
extern "C" void kernel_launch(void* const* d_in, const int* in_sizes, int n_in,
                              void* d_out, int out_size) {
    const float* c_feat = (const float*)d_in[0];
    const float* s_feat = (const float*)d_in[1];
    const void* c_mask = d_in[2];
    const void* s_mask = d_in[3];
    float* out = (float*)d_out;

    cudaFuncSetAttribute(k_solveT, cudaFuncAttributeMaxDynamicSharedMemorySize, 32896 * 4);

    k_sniff<<<1, 256>>>((const unsigned*)c_mask);

    k_hist<<<NBLK, 256>>>(c_mask, 0);
    k_hist<<<NBLK, 256>>>(s_mask, 1);
    k_scan<<<1, 256>>>(0);
    k_scan<<<1, 256>>>(1);
    k_guide<<<1, 32>>>();
    k_perminit<<<NPAD / 256, 256>>>();
    k_scatter<<<NBLK, 256>>>(c_mask, 0);
    k_scatter<<<NBLK, 256>>>(s_mask, 1);

    dim3 gg(NPAD / 256, BB * CC);
    k_gather<<<gg, 256>>>(c_feat, 0);
    k_gather<<<gg, 256>>>(s_feat, 1);

    dim3 gm(CC, BB, NL);
    k_mean<<<gm, 256>>>(0);
    k_mean<<<gm, 256>>>(1);

    dim3 gc(10, NL * BB);
    k_cov<<<gc, 256>>>(0);
    k_cov<<<gc, 256>>>(1);

    k_chol<<<32, 256>>>();
    k_solveT<<<NL * BB, 256, 32896 * 4>>>();
    k_v<<<NL * BB, 256>>>();

    dim3 ga(NPAD / 64, 4, BB);
    k_apply<<<ga, 256>>>();

    dim3 gk(HN / 4 / 256, BB * CC);
    k_combine<<<gk, 256>>>(c_feat, out);
}